// round 4
// baseline (speedup 1.0000x reference)
#include <cuda_runtime.h>

// KAN_Convolutional_Layer: B=8, CIN=4, H=W=64, OUT=8, K2=9, G=8, Ho=Wo=62
// Single fused kernel, 128 blocks (one full wave minus 20 SMs) x 512 threads.
//   - tile 32x8 outputs per block; each thread computes 2 adjacent-row pixels
//     for all 8 outputs, over 8 of the 32 (c,g) channels (quarter = lane>>3).
//   - t-planes staged over c-pairs (16 planes at a time) to fit 48KB smem.
//   - weights reordered to [cg][f][o] with R^2 folded in.
//   - final 4-way cg reduction via warp shuffles (no extra barriers).

#define B_    8
#define CIN_  4
#define H_    64
#define W_    64
#define OUT_  8
#define K2_   9
#define G_    8
#define HO_   62
#define WO_   62
#define R2_   39.0625f      // R^2, folded into weights

#define TX_     32
#define TY_     8
#define TILW    34
#define TILH    10
#define POS_    (TILH*TILW)  // 340 valid positions per plane
#define PSTR    346          // padded plane stride: 4*346 % 32 == 8 -> quarter
                             // groups land on disjoint bank octets
#define NPL     16           // planes per stage (2 c's x 8 g)
#define NTHR    512

__device__ __forceinline__ unsigned long long pack2(float lo, float hi) {
    unsigned long long r;
    asm("mov.b64 %0, {%1, %2};" : "=l"(r) : "f"(lo), "f"(hi));
    return r;
}
__device__ __forceinline__ void unpack2(unsigned long long v, float& lo, float& hi) {
    asm("mov.b64 {%0, %1}, %2;" : "=f"(lo), "=f"(hi) : "l"(v));
}
__device__ __forceinline__ unsigned long long fma2(unsigned long long a,
                                                   unsigned long long b,
                                                   unsigned long long c) {
    unsigned long long d;
    asm("fma.rn.f32x2 %0, %1, %2, %3;" : "=l"(d) : "l"(a), "l"(b), "l"(c));
    return d;
}
__device__ __forceinline__ unsigned long long add2(unsigned long long a,
                                                   unsigned long long b) {
    unsigned long long d;
    asm("add.rn.f32x2 %0, %1, %2;" : "=l"(d) : "l"(a), "l"(b));
    return d;
}

__global__ void __launch_bounds__(NTHR, 1)
kan_fused_kernel(const float* __restrict__ x,
                 const float* __restrict__ phase_low,
                 const float* __restrict__ phase_high,
                 const float* __restrict__ weight,
                 const float* __restrict__ bias,
                 float* __restrict__ out) {
    __shared__ __align__(16) float tsh[NPL * PSTR];        // 5536 f = 22.1 KB
    __shared__ __align__(16) float wsh[32 * K2_ * OUT_];   // 2304 f =  9.2 KB
    __shared__ float bsh[OUT_];

    const int b   = blockIdx.z;
    const int x0  = blockIdx.x * TX_;   // 0 or 32
    const int y0  = blockIdx.y * TY_;   // 0..56
    const int tid = threadIdx.x;

    // ---- weight reorder with R^2 folded: wsh[cg*72 + f*8 + o], cg = c*8+g
    for (int i = tid; i < 32 * K2_ * OUT_; i += NTHR) {
        int o  = i & 7;
        int f  = (i >> 3) % K2_;
        int cg = i / (OUT_ * K2_);
        int g  = cg & 7;
        int c  = cg >> 3;
        wsh[i] = weight[((o * CIN_ + c) * K2_ + f) * G_ + g] * R2_;
    }
    if (tid < OUT_) {
        float s = 0.0f;
#pragma unroll
        for (int c = 0; c < CIN_; c++) s += bias[tid * CIN_ + c];
        bsh[tid] = s;
    }

    float pl[G_], ph[G_];
#pragma unroll
    for (int g = 0; g < G_; g++) {
        pl[g] = __ldg(&phase_low[g]);    // broadcast over (o,c,f) by construction
        ph[g] = __ldg(&phase_high[g]);
    }

    // ---- lane/geometry decomposition
    const int w    = tid >> 5;           // warp 0..15
    const int l    = tid & 31;
    const int q    = l >> 3;             // cg quarter 0..3 inside warp
    const int sub  = l & 7;
    const int pair = w * 8 + sub;        // pixel-pair index 0..127
    const int tx   = pair & 31;
    const int typ  = pair >> 5;          // 0..3 -> rows 2*typ, 2*typ+1

    unsigned long long accA[4] = {0, 0, 0, 0};   // pixel A: o-pairs
    unsigned long long accB[4] = {0, 0, 0, 0};   // pixel B

#pragma unroll
    for (int s = 0; s < 2; s++) {        // stage over c-pairs {0,1}, {2,3}
        // -- spline fill: planes p = c_local*8+g for c = 2s+c_local
        __syncthreads();                 // prior stage's reads complete
#pragma unroll
        for (int it = 0; it < 2; it++) {
            int i = tid + it * NTHR;
            if (i < 2 * POS_) {
                int cl  = i >= POS_;
                int pos = i - cl * POS_;
                int row = pos / TILW;
                int col = pos - row * TILW;
                int gy = y0 + row, gx = x0 + col;
                float xv = 0.0f;
                if (gy < H_ && gx < W_)
                    xv = __ldg(&x[((b * CIN_ + 2 * s + cl) * H_ + gy) * W_ + gx]);
#pragma unroll
                for (int g = 0; g < G_; g++) {
                    float a = fmaxf(xv - pl[g], 0.0f);
                    float d = fmaxf(ph[g] - xv, 0.0f);
                    float m = a * d;
                    tsh[(cl * G_ + g) * PSTR + pos] = m * m;  // R^2 in weights
                }
            }
        }
        __syncthreads();

        // -- conv: quarter q handles planes q*4 .. q*4+3 of this stage
#pragma unroll
        for (int i = 0; i < 4; i++) {
            const int p = q * 4 + i;                     // plane in stage
            const float* pb = tsh + p * PSTR + (2 * typ) * TILW + tx;
            const float* wp = wsh + (s * 16 + p) * (K2_ * OUT_);

            float tv[4][3];
#pragma unroll
            for (int r = 0; r < 4; r++)
#pragma unroll
                for (int j = 0; j < 3; j++)
                    tv[r][j] = pb[r * TILW + j];

#pragma unroll
            for (int fi = 0; fi < 3; fi++) {
#pragma unroll
                for (int fj = 0; fj < 3; fj++) {
                    unsigned long long ta = pack2(tv[fi][fj],     tv[fi][fj]);
                    unsigned long long tb = pack2(tv[fi + 1][fj], tv[fi + 1][fj]);
                    const ulonglong2* w2 =
                        reinterpret_cast<const ulonglong2*>(wp + (fi * 3 + fj) * OUT_);
                    ulonglong2 wa = w2[0];   // o0..o3
                    ulonglong2 wb = w2[1];   // o4..o7
                    accA[0] = fma2(ta, wa.x, accA[0]);
                    accA[1] = fma2(ta, wa.y, accA[1]);
                    accA[2] = fma2(ta, wb.x, accA[2]);
                    accA[3] = fma2(ta, wb.y, accA[3]);
                    accB[0] = fma2(tb, wa.x, accB[0]);
                    accB[1] = fma2(tb, wa.y, accB[1]);
                    accB[2] = fma2(tb, wb.x, accB[2]);
                    accB[3] = fma2(tb, wb.y, accB[3]);
                }
            }
        }
    }

    // ---- intra-warp reduction across the 4 cg quarters (xor 8, then xor 16)
#pragma unroll
    for (int k = 0; k < 4; k++) {
        accA[k] = add2(accA[k], __shfl_xor_sync(0xffffffffu, accA[k], 8));
        accB[k] = add2(accB[k], __shfl_xor_sync(0xffffffffu, accB[k], 8));
    }
#pragma unroll
    for (int k = 0; k < 4; k++) {
        accA[k] = add2(accA[k], __shfl_xor_sync(0xffffffffu, accA[k], 16));
        accB[k] = add2(accB[k], __shfl_xor_sync(0xffffffffu, accB[k], 16));
    }

    if (q == 0) {
        const int ox  = x0 + tx;
        const int oy0 = y0 + 2 * typ;
        float vA[OUT_], vB[OUT_];
#pragma unroll
        for (int k = 0; k < 4; k++) {
            unpack2(accA[k], vA[2 * k], vA[2 * k + 1]);
            unpack2(accB[k], vB[2 * k], vB[2 * k + 1]);
        }
        if (ox < WO_) {
            if (oy0 < HO_) {
#pragma unroll
                for (int o = 0; o < OUT_; o++)
                    out[((b * OUT_ + o) * HO_ + oy0) * WO_ + ox] = vA[o] + bsh[o];
            }
            if (oy0 + 1 < HO_) {
#pragma unroll
                for (int o = 0; o < OUT_; o++)
                    out[((b * OUT_ + o) * HO_ + oy0 + 1) * WO_ + ox] = vB[o] + bsh[o];
            }
        }
    }
}

// ---------------------------------------------------------------------------
extern "C" void kernel_launch(void* const* d_in, const int* in_sizes, int n_in,
                              void* d_out, int out_size) {
    const float* x          = (const float*)d_in[0];
    const float* phase_low  = (const float*)d_in[1];
    const float* phase_high = (const float*)d_in[2];
    const float* weight     = (const float*)d_in[3];
    const float* bias       = (const float*)d_in[4];
    float* out = (float*)d_out;

    dim3 grid((WO_ + TX_ - 1) / TX_,     // 2
              (HO_ + TY_ - 1) / TY_,     // 8
              B_);                       // 8  -> 128 blocks x 512 threads
    kan_fused_kernel<<<grid, NTHR>>>(x, phase_low, phase_high, weight, bias, out);
}